// round 11
// baseline (speedup 1.0000x reference)
#include <cuda_runtime.h>
#include <cuda_fp16.h>
#include <cstdint>
#include <cstddef>

#define B_ 4
#define T_ 4096
#define C_ 512
#define H_ 64
#define NEGB (-1e30f)

__device__ __half g_q[B_*T_*H_];
__device__ __half g_k[B_*T_*H_];
__device__ __half g_v[B_*T_*H_];
__device__ float  g_pO[4ull * B_*T_*H_];   // per-segment partial O (slot s)
__device__ float  g_pl[4 * B_*T_];         // per-segment partial l

// ---------------- helpers ----------------
__device__ __forceinline__ float ex2f(float x) {
    float y; asm("ex2.approx.ftz.f32 %0, %1;" : "=f"(y) : "f"(x)); return y;
}
__device__ __forceinline__ void mma16(float* d, const uint32_t* a, const uint32_t* b) {
    asm("mma.sync.aligned.m16n8k16.row.col.f32.f16.f16.f32 "
        "{%0,%1,%2,%3}, {%4,%5,%6,%7}, {%8,%9}, {%0,%1,%2,%3};"
        : "+f"(d[0]), "+f"(d[1]), "+f"(d[2]), "+f"(d[3])
        : "r"(a[0]), "r"(a[1]), "r"(a[2]), "r"(a[3]), "r"(b[0]), "r"(b[1]));
}

// ---------------- QKV projection: 3xFP16 split mma, 2 CTAs/SM ----------------
// 256 CTAs x 64 rows, 256 threads = 8 warps.
// Warp = (rowgrp = w>>2) 32 rows x (colgrp = w&3) 48 cols: 2 m-tiles x 6 n-tiles.
__global__ __launch_bounds__(256, 2) void qkv_kernel(
    const float* __restrict__ x,
    const float* __restrict__ Wq, const float* __restrict__ bq,
    const float* __restrict__ Wk, const float* __restrict__ bk,
    const float* __restrict__ Wv, const float* __restrict__ bv)
{
    extern __shared__ __half qsm[];
    __half* xh  = qsm;                 // [64][72]
    __half* xl  = qsm + 4608;          // [64][72]
    __half* wTh = qsm + 9216;          // [192 n][72 k]
    __half* wTl = qsm + 23040;         // [192 n][72 k]  total 36864 halves = 73728 B

    const int t = threadIdx.x, w = t >> 5, lane = t & 31;
    const int kq = lane >> 2, lj = lane & 3;
    const int rowgrp = w >> 2, colgrp = w & 3;
    const int row0 = blockIdx.x << 6;

    float o[12][4];   // [mt*6+nt][4]
    #pragma unroll
    for (int i = 0; i < 12; ++i)
        #pragma unroll
        for (int u = 0; u < 4; ++u) o[i][u] = 0.f;

    for (int kb = 0; kb < 8; ++kb) {
        __syncthreads();
        // ---- stage x slab [64 x 64], hi/lo fp16 ----
        #pragma unroll
        for (int e = t; e < 1024; e += 256) {
            int row = e >> 4, c4 = (e & 15) << 2;
            float4 v = *(const float4*)(x + (size_t)(row0 + row) * C_ + (kb << 6) + c4);
            __half h0 = __float2half_rn(v.x), h1 = __float2half_rn(v.y);
            __half h2 = __float2half_rn(v.z), h3 = __float2half_rn(v.w);
            __half l0 = __float2half_rn(v.x - __half2float(h0));
            __half l1 = __float2half_rn(v.y - __half2float(h1));
            __half l2 = __float2half_rn(v.z - __half2float(h2));
            __half l3 = __float2half_rn(v.w - __half2float(h3));
            *(__half2*)(xh + row * 72 + c4)     = __halves2half2(h0, h1);
            *(__half2*)(xh + row * 72 + c4 + 2) = __halves2half2(h2, h3);
            *(__half2*)(xl + row * 72 + c4)     = __halves2half2(l0, l1);
            *(__half2*)(xl + row * 72 + c4 + 2) = __halves2half2(l2, l3);
        }
        // ---- stage W^T slab [192 n x 64 k], k-pairs packed, hi/lo ----
        #pragma unroll
        for (int e = t; e < 1536; e += 256) {
            int k2 = e & 31, ng = e >> 5;
            int n0 = ng << 2;
            int m = n0 >> 6, col = n0 & 63;
            const float* W = (m == 0) ? Wq : (m == 1) ? Wk : Wv;
            float4 v0 = *(const float4*)(W + (size_t)((kb << 6) + 2 * k2)     * H_ + col);
            float4 v1 = *(const float4*)(W + (size_t)((kb << 6) + 2 * k2 + 1) * H_ + col);
            const float e0[4] = {v0.x, v0.y, v0.z, v0.w};
            const float e1[4] = {v1.x, v1.y, v1.z, v1.w};
            #pragma unroll
            for (int j = 0; j < 4; ++j) {
                __half ha = __float2half_rn(e0[j]);
                __half hb = __float2half_rn(e1[j]);
                __half la = __float2half_rn(e0[j] - __half2float(ha));
                __half lb = __float2half_rn(e1[j] - __half2float(hb));
                *(__half2*)(wTh + (n0 + j) * 72 + 2 * k2) = __halves2half2(ha, hb);
                *(__half2*)(wTl + (n0 + j) * 72 + 2 * k2) = __halves2half2(la, lb);
            }
        }
        __syncthreads();

        // ---- compute: 4 k-steps of 16 ----
        #pragma unroll
        for (int kt = 0; kt < 4; ++kt) {
            const int d0 = (kt << 4) + (lj << 1);
            uint32_t ah[2][4], al[2][4];
            #pragma unroll
            for (int mt = 0; mt < 2; ++mt) {
                const int r0 = (rowgrp << 5) + (mt << 4) + kq;
                ah[mt][0] = *(const uint32_t*)(xh + r0 * 72 + d0);
                ah[mt][1] = *(const uint32_t*)(xh + (r0 + 8) * 72 + d0);
                ah[mt][2] = *(const uint32_t*)(xh + r0 * 72 + d0 + 8);
                ah[mt][3] = *(const uint32_t*)(xh + (r0 + 8) * 72 + d0 + 8);
                al[mt][0] = *(const uint32_t*)(xl + r0 * 72 + d0);
                al[mt][1] = *(const uint32_t*)(xl + (r0 + 8) * 72 + d0);
                al[mt][2] = *(const uint32_t*)(xl + r0 * 72 + d0 + 8);
                al[mt][3] = *(const uint32_t*)(xl + (r0 + 8) * 72 + d0 + 8);
            }
            #pragma unroll
            for (int nt = 0; nt < 6; ++nt) {
                const int n = colgrp * 48 + (nt << 3) + kq;
                uint32_t bh[2], bl[2];
                bh[0] = *(const uint32_t*)(wTh + n * 72 + d0);
                bh[1] = *(const uint32_t*)(wTh + n * 72 + d0 + 8);
                bl[0] = *(const uint32_t*)(wTl + n * 72 + d0);
                bl[1] = *(const uint32_t*)(wTl + n * 72 + d0 + 8);
                #pragma unroll
                for (int mt = 0; mt < 2; ++mt) {
                    mma16(o[mt * 6 + nt], ah[mt], bh);
                    mma16(o[mt * 6 + nt], ah[mt], bl);
                    mma16(o[mt * 6 + nt], al[mt], bh);
                }
            }
        }
    }

    // ---- epilogue: bias, scale, fp16 store ----
    const float QS = 0.125f * 1.4426950408889634f;  // (1/sqrt(64)) * log2(e)
    #pragma unroll
    for (int mt = 0; mt < 2; ++mt) {
        const int rA = row0 + (rowgrp << 5) + (mt << 4) + kq;
        const int rB = rA + 8;
        #pragma unroll
        for (int nt = 0; nt < 6; ++nt) {
            const int cb = colgrp * 48 + (nt << 3);
            const int m = cb >> 6;
            const int cc = (cb & 63) + (lj << 1);
            const float* bias = (m == 0) ? bq : (m == 1) ? bk : bv;
            __half* dst = (m == 0) ? g_q : (m == 1) ? g_k : g_v;
            const float b0 = bias[cc], b1 = bias[cc + 1];
            float v0 = o[mt * 6 + nt][0] + b0, v1 = o[mt * 6 + nt][1] + b1;
            float v2 = o[mt * 6 + nt][2] + b0, v3 = o[mt * 6 + nt][3] + b1;
            if (m == 0) { v0 *= QS; v1 *= QS; v2 *= QS; v3 *= QS; }
            *(__half2*)(dst + (size_t)rA * H_ + cc) = __floats2half2_rn(v0, v1);
            *(__half2*)(dst + (size_t)rB * H_ + cc) = __floats2half2_rn(v2, v3);
        }
    }
}

// ---------------- schedule: 80 (qtile, seg) units, heaviest first ----------------
__constant__ unsigned char c_sched[80] = {
    28, 60, 61, 88, 92, 93, 94, 120, 121, 124, 125, 126, 127,
    56, 57, 84, 85, 89, 90, 112, 113, 116, 117, 118, 119, 122, 123,
    24, 52, 53, 76, 80, 81, 82, 86, 104, 105, 108, 109, 110, 111, 114, 115,
    48, 49, 72, 73, 77, 78, 96, 97, 100, 101, 102, 103, 106, 107,
    20, 44, 45, 64, 68, 69, 70, 74, 98, 99,
    40, 41, 65, 66,
    16, 36, 37,
    32, 33,
    12, 8, 4, 0
};

// K rows copied fp16 [64 key][72 d]; V transposed fp16 [64 h][72 key] (key-pairs).
__device__ __forceinline__ void load_kv_h(
    __half* Kb, __half* Vb, const __half* kc, const __half* vc, int t)
{
    #pragma unroll
    for (int e = t; e < 512; e += 256) {
        int row = e >> 3, c8 = (e & 7) << 3;
        *(uint4*)(Kb + row * 72 + c8) = *(const uint4*)(kc + row * 64 + c8);
    }
    #pragma unroll
    for (int e = t; e < 512; e += 256) {
        int k2 = e & 31, h4 = (e >> 5) << 2;
        uint2 a0 = *(const uint2*)(vc + (size_t)(2 * k2) * 64 + h4);
        uint2 a1 = *(const uint2*)(vc + (size_t)(2 * k2 + 1) * 64 + h4);
        uint32_t o0 = (a0.x & 0xFFFFu) | (a1.x << 16);
        uint32_t o1 = (a0.x >> 16)     | (a1.x & 0xFFFF0000u);
        uint32_t o2 = (a0.y & 0xFFFFu) | (a1.y << 16);
        uint32_t o3 = (a0.y >> 16)     | (a1.y & 0xFFFF0000u);
        *(uint32_t*)(Vb + (h4 + 0) * 72 + 2 * k2) = o0;
        *(uint32_t*)(Vb + (h4 + 1) * 72 + 2 * k2) = o1;
        *(uint32_t*)(Vb + (h4 + 2) * 72 + 2 * k2) = o2;
        *(uint32_t*)(Vb + (h4 + 3) * 72 + 2 * k2) = o3;
    }
}

// ---------------- fp16 flash attention, partials to slot buffers ----------------
__global__ __launch_bounds__(256, 2) void attn_kernel(const unsigned char* __restrict__ pmask)
{
    extern __shared__ __half smh[];
    __half* Ks = smh;                    // 2 x [64][72]
    __half* Vt = smh + 9216;             // 2 x [64][72]
    float* pmfs = (float*)(smh + 18432); // 2 x [64]

    const int t = threadIdx.x, w = t >> 5, lane = t & 31;
    const int kq = lane >> 2, lj = lane & 3;

    const int bid = blockIdx.x;
    const int e = c_sched[bid >> 2];
    const int qt = e >> 2, seg = e & 3;
    const int b = bid & 3;
    const int nseg = (qt >> 3) + 1;
    const int n = 2 * (qt + 1);
    const int base = n / nseg, rem = n - base * nseg;
    const int cnt = base + (seg < rem ? 1 : 0);
    const int c0 = seg * base + (seg < rem ? seg : rem);

    const int q0 = qt << 7;
    const int qbase = w << 4;
    const int qA = q0 + qbase + kq;
    const int qB = qA + 8;

    const __half* kg = g_k + (size_t)b * T_ * H_;
    const __half* vg = g_v + (size_t)b * T_ * H_;

    // ---- Q A-fragments straight from gmem (constant across chunks) ----
    uint32_t qa[4][4];
    {
        const __half* qra = g_q + ((size_t)b * T_ + qA) * H_;
        const __half* qrb = g_q + ((size_t)b * T_ + qB) * H_;
        #pragma unroll
        for (int kt = 0; kt < 4; ++kt) {
            const int d0 = (kt << 4) + (lj << 1);
            qa[kt][0] = *(const uint32_t*)(qra + d0);
            qa[kt][1] = *(const uint32_t*)(qrb + d0);
            qa[kt][2] = *(const uint32_t*)(qra + d0 + 8);
            qa[kt][3] = *(const uint32_t*)(qrb + d0 + 8);
        }
    }

    load_kv_h(Ks, Vt, kg + (size_t)(c0 << 6) * 64, vg + (size_t)(c0 << 6) * 64, t);
    if (t < 64) pmfs[t] = pmask[(size_t)b * T_ + (c0 << 6) + t] ? NEGB : 0.f;
    __syncthreads();

    float o[8][4];
    #pragma unroll
    for (int nt = 0; nt < 8; ++nt)
        #pragma unroll
        for (int u = 0; u < 4; ++u) o[nt][u] = 0.f;
    float lacc0 = 0.f, lacc1 = 0.f;

    for (int i = 0; i < cnt; ++i) {
        const int buf = i & 1, nbuf = buf ^ 1;
        const int k0 = (c0 + i) << 6;
        if (i) __syncthreads();

        if (i + 1 < cnt) {
            const int k1 = k0 + 64;
            load_kv_h(Ks + nbuf * 4608, Vt + nbuf * 4608,
                      kg + (size_t)k1 * 64, vg + (size_t)k1 * 64, t);
            if (t < 64) pmfs[nbuf * 64 + t] = pmask[(size_t)b * T_ + k1 + t] ? NEGB : 0.f;
        }

        const __half* K = Ks + buf * 4608;
        const __half* V = Vt + buf * 4608;
        const float* pm = pmfs + buf * 64;

        // ---- S[16q x 64key] ----
        float st[8][4];
        #pragma unroll
        for (int nt = 0; nt < 8; ++nt)
            #pragma unroll
            for (int u = 0; u < 4; ++u) st[nt][u] = 0.f;
        #pragma unroll
        for (int kt = 0; kt < 4; ++kt) {
            const int d0 = (kt << 4) + (lj << 1);
            #pragma unroll
            for (int nt = 0; nt < 8; ++nt) {
                const int krow = (nt << 3) + kq;
                uint32_t bb[2];
                bb[0] = *(const uint32_t*)(K + krow * 72 + d0);
                bb[1] = *(const uint32_t*)(K + krow * 72 + d0 + 8);
                mma16(st[nt], qa[kt], bb);
            }
        }

        // ---- softmax (no max) + pack P a-frags in registers ----
        const bool needmask = (k0 + 63) > (q0 + qbase);
        uint32_t pa[4][4];
        #pragma unroll
        for (int nt = 0; nt < 8; ++nt) {
            const int key0 = k0 + (nt << 3) + (lj << 1);
            const float pm0 = pm[(nt << 3) + (lj << 1)];
            const float pm1 = pm[(nt << 3) + (lj << 1) + 1];
            float p0 = ex2f(st[nt][0] + pm0);
            float p1 = ex2f(st[nt][1] + pm1);
            float p2 = ex2f(st[nt][2] + pm0);
            float p3 = ex2f(st[nt][3] + pm1);
            if (needmask) {
                if (key0 > qA)     p0 = 0.f;
                if (key0 + 1 > qA) p1 = 0.f;
                if (key0 > qB)     p2 = 0.f;
                if (key0 + 1 > qB) p3 = 0.f;
            }
            __half2 h01 = __floats2half2_rn(p0, p1);
            __half2 h23 = __floats2half2_rn(p2, p3);
            float2 f01 = __half22float2(h01);
            float2 f23 = __half22float2(h23);
            lacc0 += f01.x + f01.y;
            lacc1 += f23.x + f23.y;
            const int ktp = nt >> 1;
            if ((nt & 1) == 0) {
                pa[ktp][0] = *(uint32_t*)&h01;
                pa[ktp][1] = *(uint32_t*)&h23;
            } else {
                pa[ktp][2] = *(uint32_t*)&h01;
                pa[ktp][3] = *(uint32_t*)&h23;
            }
        }

        // ---- O += P[16q x 64k] x V[64k x 64h] ----
        #pragma unroll
        for (int ktp = 0; ktp < 4; ++ktp) {
            const int d0 = (ktp << 4) + (lj << 1);
            #pragma unroll
            for (int nt = 0; nt < 8; ++nt) {
                const int hrow = (nt << 3) + kq;
                uint32_t bb[2];
                bb[0] = *(const uint32_t*)(V + hrow * 72 + d0);
                bb[1] = *(const uint32_t*)(V + hrow * 72 + d0 + 8);
                mma16(o[nt], pa[ktp], bb);
            }
        }
    }

    // ---- partial l: reduce within 4-lane groups, plain store ----
    lacc0 += __shfl_xor_sync(0xFFFFFFFFu, lacc0, 1);
    lacc0 += __shfl_xor_sync(0xFFFFFFFFu, lacc0, 2);
    lacc1 += __shfl_xor_sync(0xFFFFFFFFu, lacc1, 1);
    lacc1 += __shfl_xor_sync(0xFFFFFFFFu, lacc1, 2);
    if (lj == 0) {
        g_pl[seg * B_ * T_ + (size_t)b * T_ + qA] = lacc0;
        g_pl[seg * B_ * T_ + (size_t)b * T_ + qB] = lacc1;
    }

    // ---- partial O: plain stores to slot buffer ----
    {
        float* oA = g_pO + (size_t)seg * B_ * T_ * H_ + ((size_t)b * T_ + qA) * 64;
        float* oB = g_pO + (size_t)seg * B_ * T_ * H_ + ((size_t)b * T_ + qB) * 64;
        #pragma unroll
        for (int nt = 0; nt < 8; ++nt) {
            const int h = (nt << 3) + (lj << 1);
            *(float2*)(oA + h) = make_float2(o[nt][0], o[nt][1]);
            *(float2*)(oB + h) = make_float2(o[nt][2], o[nt][3]);
        }
    }
}

// ---------------- finalize: out = (sum slots O) / (sum slots l) ----------------
__global__ __launch_bounds__(256) void fin_kernel(float* __restrict__ out)
{
    const int idx = blockIdx.x * 256 + threadIdx.x;   // 262144
    const int bt = idx >> 4, h4 = (idx & 15) << 2;
    const int qt = (bt & (T_ - 1)) >> 7;
    const int nseg = (qt >> 3) + 1;

    float l = g_pl[bt];
    float4 v = *(const float4*)(g_pO + (size_t)bt * 64 + h4);
    for (int s = 1; s < nseg; ++s) {
        l += g_pl[s * B_ * T_ + bt];
        const float4 u = *(const float4*)(g_pO + (size_t)s * B_ * T_ * H_ + (size_t)bt * 64 + h4);
        v.x += u.x; v.y += u.y; v.z += u.z; v.w += u.w;
    }
    const float inv = 1.f / l;
    v.x *= inv; v.y *= inv; v.z *= inv; v.w *= inv;
    *(float4*)(out + (size_t)bt * 64 + h4) = v;
}

// ---------------------------------------------------------------------------
extern "C" void kernel_launch(void* const* d_in, const int* in_sizes, int n_in,
                              void* d_out, int out_size)
{
    const float*         x  = (const float*)d_in[0];
    const unsigned char* pm = (const unsigned char*)d_in[1];
    const float*         Wq = (const float*)d_in[2];
    const float*         bq = (const float*)d_in[3];
    const float*         Wk = (const float*)d_in[4];
    const float*         bk = (const float*)d_in[5];
    const float*         Wv = (const float*)d_in[6];
    const float*         bv = (const float*)d_in[7];
    float* out = (float*)d_out;

    const int qkv_smem = 36864 * 2;    // 73728 B
    cudaFuncSetAttribute(qkv_kernel,
                         cudaFuncAttributeMaxDynamicSharedMemorySize, qkv_smem);
    qkv_kernel<<<(B_ * T_) / 64, 256, qkv_smem>>>(x, Wq, bq, Wk, bk, Wv, bv);

    const int attn_smem = 18432 * 2 + 512;   // 37376 B
    cudaFuncSetAttribute(attn_kernel,
                         cudaFuncAttributeMaxDynamicSharedMemorySize, attn_smem);
    attn_kernel<<<320, 256, attn_smem>>>(pm);

    fin_kernel<<<1024, 256>>>(out);
}

// round 13
// speedup vs baseline: 1.1842x; 1.1842x over previous
#include <cuda_runtime.h>
#include <cuda_fp16.h>
#include <cstdint>
#include <cstddef>

#define B_ 4
#define T_ 4096
#define C_ 512
#define H_ 64
#define NEGB (-1e30f)

__device__ __half g_q[B_*T_*H_];
__device__ __half g_k[B_*T_*H_];
__device__ __half g_v[B_*T_*H_];
__device__ __half g_wh[192 * C_];          // W^T hi, [n 0..191][k 0..511]
__device__ __half g_wl[192 * C_];          // W^T lo
__device__ float  g_pO[4ull * B_*T_*H_];   // per-segment partial O
__device__ float  g_pl[4 * B_*T_];         // per-segment partial l

// ---------------- helpers ----------------
__device__ __forceinline__ float ex2f(float x) {
    float y; asm("ex2.approx.ftz.f32 %0, %1;" : "=f"(y) : "f"(x)); return y;
}
__device__ __forceinline__ void mma16(float* d, const uint32_t* a, const uint32_t* b) {
    asm("mma.sync.aligned.m16n8k16.row.col.f32.f16.f16.f32 "
        "{%0,%1,%2,%3}, {%4,%5,%6,%7}, {%8,%9}, {%0,%1,%2,%3};"
        : "+f"(d[0]), "+f"(d[1]), "+f"(d[2]), "+f"(d[3])
        : "r"(a[0]), "r"(a[1]), "r"(a[2]), "r"(a[3]), "r"(b[0]), "r"(b[1]));
}

// ---------------- prep: split W into hi/lo fp16, transposed [n][k] ----------------
__global__ __launch_bounds__(256) void prep_kernel(
    const float* __restrict__ Wq, const float* __restrict__ Wk, const float* __restrict__ Wv)
{
    const int idx = blockIdx.x * 256 + threadIdx.x;   // 98304 = 192 * 512
    const int n = idx >> 9, k = idx & 511;
    const int m = n >> 6, col = n & 63;
    const float* W = (m == 0) ? Wq : (m == 1) ? Wk : Wv;
    const float v = W[(size_t)k * H_ + col];
    const __half h = __float2half_rn(v);
    g_wh[idx] = h;
    g_wl[idx] = __float2half_rn(v - __half2float(h));
}

// ---------------- QKV projection: 3xFP16 split mma (R10 shape, copy-only W) ----------
// 128 CTAs x 128 rows, 256 threads = 8 warps.
// Warp = (rowgrp = w>>2) 64 rows x (colgrp = w&3) 48 cols: 4 m-tiles x 6 n-tiles.
__global__ __launch_bounds__(256) void qkv_kernel(
    const float* __restrict__ x,
    const float* __restrict__ bq, const float* __restrict__ bk, const float* __restrict__ bv)
{
    extern __shared__ __half qsm[];
    __half* xh  = qsm;                 // [128][72]
    __half* xl  = qsm + 9216;          // [128][72]
    __half* wTh = qsm + 18432;         // [192 n][72 k]
    __half* wTl = qsm + 32256;         // [192 n][72 k]   total 46080 halves = 92160 B

    const int t = threadIdx.x, w = t >> 5, lane = t & 31;
    const int kq = lane >> 2, lj = lane & 3;
    const int rowgrp = w >> 2, colgrp = w & 3;
    const int row0 = blockIdx.x << 7;

    float o[24][4];   // [mt*6+nt][4]
    #pragma unroll
    for (int i = 0; i < 24; ++i)
        #pragma unroll
        for (int u = 0; u < 4; ++u) o[i][u] = 0.f;

    for (int kb = 0; kb < 8; ++kb) {
        __syncthreads();
        // ---- stage x slab [128 x 64], hi/lo fp16 (split in-kernel: not redundant) ----
        #pragma unroll
        for (int e = t; e < 2048; e += 256) {
            int row = e >> 4, c4 = (e & 15) << 2;
            float4 v = *(const float4*)(x + (size_t)(row0 + row) * C_ + (kb << 6) + c4);
            __half h0 = __float2half_rn(v.x), h1 = __float2half_rn(v.y);
            __half h2 = __float2half_rn(v.z), h3 = __float2half_rn(v.w);
            __half l0 = __float2half_rn(v.x - __half2float(h0));
            __half l1 = __float2half_rn(v.y - __half2float(h1));
            __half l2 = __float2half_rn(v.z - __half2float(h2));
            __half l3 = __float2half_rn(v.w - __half2float(h3));
            *(__half2*)(xh + row * 72 + c4)     = __halves2half2(h0, h1);
            *(__half2*)(xh + row * 72 + c4 + 2) = __halves2half2(h2, h3);
            *(__half2*)(xl + row * 72 + c4)     = __halves2half2(l0, l1);
            *(__half2*)(xl + row * 72 + c4 + 2) = __halves2half2(l2, l3);
        }
        // ---- stage W^T slab [192 n x 64 k]: pure uint4 copies from pre-split ----
        #pragma unroll
        for (int e = t; e < 1536; e += 256) {
            int n = e >> 3, u8 = (e & 7) << 3;
            *(uint4*)(wTh + n * 72 + u8) = *(const uint4*)(g_wh + n * C_ + (kb << 6) + u8);
            *(uint4*)(wTl + n * 72 + u8) = *(const uint4*)(g_wl + n * C_ + (kb << 6) + u8);
        }
        __syncthreads();

        // ---- compute: 4 k-steps of 16 ----
        #pragma unroll
        for (int kt = 0; kt < 4; ++kt) {
            const int d0 = (kt << 4) + (lj << 1);
            uint32_t ah[4][4], al[4][4];
            #pragma unroll
            for (int mt = 0; mt < 4; ++mt) {
                const int r0 = (rowgrp << 6) + (mt << 4) + kq;
                ah[mt][0] = *(const uint32_t*)(xh + r0 * 72 + d0);
                ah[mt][1] = *(const uint32_t*)(xh + (r0 + 8) * 72 + d0);
                ah[mt][2] = *(const uint32_t*)(xh + r0 * 72 + d0 + 8);
                ah[mt][3] = *(const uint32_t*)(xh + (r0 + 8) * 72 + d0 + 8);
                al[mt][0] = *(const uint32_t*)(xl + r0 * 72 + d0);
                al[mt][1] = *(const uint32_t*)(xl + (r0 + 8) * 72 + d0);
                al[mt][2] = *(const uint32_t*)(xl + r0 * 72 + d0 + 8);
                al[mt][3] = *(const uint32_t*)(xl + (r0 + 8) * 72 + d0 + 8);
            }
            #pragma unroll
            for (int nt = 0; nt < 6; ++nt) {
                const int n = colgrp * 48 + (nt << 3) + kq;
                uint32_t bh[2], bl[2];
                bh[0] = *(const uint32_t*)(wTh + n * 72 + d0);
                bh[1] = *(const uint32_t*)(wTh + n * 72 + d0 + 8);
                bl[0] = *(const uint32_t*)(wTl + n * 72 + d0);
                bl[1] = *(const uint32_t*)(wTl + n * 72 + d0 + 8);
                #pragma unroll
                for (int mt = 0; mt < 4; ++mt) {
                    mma16(o[mt * 6 + nt], ah[mt], bh);
                    mma16(o[mt * 6 + nt], ah[mt], bl);
                    mma16(o[mt * 6 + nt], al[mt], bh);
                }
            }
        }
    }

    // ---- epilogue: bias, scale, fp16 store ----
    const float QS = 0.125f * 1.4426950408889634f;  // (1/sqrt(64)) * log2(e)
    #pragma unroll
    for (int mt = 0; mt < 4; ++mt) {
        const int rA = row0 + (rowgrp << 6) + (mt << 4) + kq;
        const int rB = rA + 8;
        #pragma unroll
        for (int nt = 0; nt < 6; ++nt) {
            const int cb = colgrp * 48 + (nt << 3);
            const int m = cb >> 6;
            const int cc = (cb & 63) + (lj << 1);
            const float* bias = (m == 0) ? bq : (m == 1) ? bk : bv;
            __half* dst = (m == 0) ? g_q : (m == 1) ? g_k : g_v;
            const float b0 = bias[cc], b1 = bias[cc + 1];
            float v0 = o[mt * 6 + nt][0] + b0, v1 = o[mt * 6 + nt][1] + b1;
            float v2 = o[mt * 6 + nt][2] + b0, v3 = o[mt * 6 + nt][3] + b1;
            if (m == 0) { v0 *= QS; v1 *= QS; v2 *= QS; v3 *= QS; }
            *(__half2*)(dst + (size_t)rA * H_ + cc) = __floats2half2_rn(v0, v1);
            *(__half2*)(dst + (size_t)rB * H_ + cc) = __floats2half2_rn(v2, v3);
        }
    }
}

// ---------------- schedule: 80 (qtile, seg) units, heaviest first ----------------
__constant__ unsigned char c_sched[80] = {
    28, 60, 61, 88, 92, 93, 94, 120, 121, 124, 125, 126, 127,
    56, 57, 84, 85, 89, 90, 112, 113, 116, 117, 118, 119, 122, 123,
    24, 52, 53, 76, 80, 81, 82, 86, 104, 105, 108, 109, 110, 111, 114, 115,
    48, 49, 72, 73, 77, 78, 96, 97, 100, 101, 102, 103, 106, 107,
    20, 44, 45, 64, 68, 69, 70, 74, 98, 99,
    40, 41, 65, 66,
    16, 36, 37,
    32, 33,
    12, 8, 4, 0
};

// K rows copied fp16 [64 key][72 d]; V transposed fp16 [64 h][72 key] (key-pairs).
__device__ __forceinline__ void load_kv_h(
    __half* Kb, __half* Vb, const __half* kc, const __half* vc, int t)
{
    #pragma unroll
    for (int e = t; e < 512; e += 256) {
        int row = e >> 3, c8 = (e & 7) << 3;
        *(uint4*)(Kb + row * 72 + c8) = *(const uint4*)(kc + row * 64 + c8);
    }
    #pragma unroll
    for (int e = t; e < 512; e += 256) {
        int k2 = e & 31, h4 = (e >> 5) << 2;
        uint2 a0 = *(const uint2*)(vc + (size_t)(2 * k2) * 64 + h4);
        uint2 a1 = *(const uint2*)(vc + (size_t)(2 * k2 + 1) * 64 + h4);
        uint32_t o0 = (a0.x & 0xFFFFu) | (a1.x << 16);
        uint32_t o1 = (a0.x >> 16)     | (a1.x & 0xFFFF0000u);
        uint32_t o2 = (a0.y & 0xFFFFu) | (a1.y << 16);
        uint32_t o3 = (a0.y >> 16)     | (a1.y & 0xFFFF0000u);
        *(uint32_t*)(Vb + (h4 + 0) * 72 + 2 * k2) = o0;
        *(uint32_t*)(Vb + (h4 + 1) * 72 + 2 * k2) = o1;
        *(uint32_t*)(Vb + (h4 + 2) * 72 + 2 * k2) = o2;
        *(uint32_t*)(Vb + (h4 + 3) * 72 + 2 * k2) = o3;
    }
}

// ---------------- fp16 flash attention, partials to slot buffers ----------------
__global__ __launch_bounds__(256, 2) void attn_kernel(const unsigned char* __restrict__ pmask)
{
    extern __shared__ __half smh[];
    __half* Ks = smh;                    // 2 x [64][72]
    __half* Vt = smh + 9216;             // 2 x [64][72]
    float* pmfs = (float*)(smh + 18432); // 2 x [64]

    const int t = threadIdx.x, w = t >> 5, lane = t & 31;
    const int kq = lane >> 2, lj = lane & 3;

    const int bid = blockIdx.x;
    const int e = c_sched[bid >> 2];
    const int qt = e >> 2, seg = e & 3;
    const int b = bid & 3;
    const int nseg = (qt >> 3) + 1;
    const int n = 2 * (qt + 1);
    const int base = n / nseg, rem = n - base * nseg;
    const int cnt = base + (seg < rem ? 1 : 0);
    const int c0 = seg * base + (seg < rem ? seg : rem);

    const int q0 = qt << 7;
    const int qbase = w << 4;
    const int qA = q0 + qbase + kq;
    const int qB = qA + 8;

    const __half* kg = g_k + (size_t)b * T_ * H_;
    const __half* vg = g_v + (size_t)b * T_ * H_;

    // ---- Q A-fragments straight from gmem (constant across chunks) ----
    uint32_t qa[4][4];
    {
        const __half* qra = g_q + ((size_t)b * T_ + qA) * H_;
        const __half* qrb = g_q + ((size_t)b * T_ + qB) * H_;
        #pragma unroll
        for (int kt = 0; kt < 4; ++kt) {
            const int d0 = (kt << 4) + (lj << 1);
            qa[kt][0] = *(const uint32_t*)(qra + d0);
            qa[kt][1] = *(const uint32_t*)(qrb + d0);
            qa[kt][2] = *(const uint32_t*)(qra + d0 + 8);
            qa[kt][3] = *(const uint32_t*)(qrb + d0 + 8);
        }
    }

    load_kv_h(Ks, Vt, kg + (size_t)(c0 << 6) * 64, vg + (size_t)(c0 << 6) * 64, t);
    if (t < 64) pmfs[t] = pmask[(size_t)b * T_ + (c0 << 6) + t] ? NEGB : 0.f;
    __syncthreads();

    float o[8][4];
    #pragma unroll
    for (int nt = 0; nt < 8; ++nt)
        #pragma unroll
        for (int u = 0; u < 4; ++u) o[nt][u] = 0.f;
    float lacc0 = 0.f, lacc1 = 0.f;

    for (int i = 0; i < cnt; ++i) {
        const int buf = i & 1, nbuf = buf ^ 1;
        const int k0 = (c0 + i) << 6;
        if (i) __syncthreads();

        if (i + 1 < cnt) {
            const int k1 = k0 + 64;
            load_kv_h(Ks + nbuf * 4608, Vt + nbuf * 4608,
                      kg + (size_t)k1 * 64, vg + (size_t)k1 * 64, t);
            if (t < 64) pmfs[nbuf * 64 + t] = pmask[(size_t)b * T_ + k1 + t] ? NEGB : 0.f;
        }

        const __half* K = Ks + buf * 4608;
        const __half* V = Vt + buf * 4608;
        const float* pm = pmfs + buf * 64;

        // ---- S[16q x 64key] ----
        float st[8][4];
        #pragma unroll
        for (int nt = 0; nt < 8; ++nt)
            #pragma unroll
            for (int u = 0; u < 4; ++u) st[nt][u] = 0.f;
        #pragma unroll
        for (int kt = 0; kt < 4; ++kt) {
            const int d0 = (kt << 4) + (lj << 1);
            #pragma unroll
            for (int nt = 0; nt < 8; ++nt) {
                const int krow = (nt << 3) + kq;
                uint32_t bb[2];
                bb[0] = *(const uint32_t*)(K + krow * 72 + d0);
                bb[1] = *(const uint32_t*)(K + krow * 72 + d0 + 8);
                mma16(st[nt], qa[kt], bb);
            }
        }

        // ---- softmax (no max) + pack P a-frags in registers ----
        const bool needmask = (k0 + 63) > (q0 + qbase);
        uint32_t pa[4][4];
        #pragma unroll
        for (int nt = 0; nt < 8; ++nt) {
            const int key0 = k0 + (nt << 3) + (lj << 1);
            const float pm0 = pm[(nt << 3) + (lj << 1)];
            const float pm1 = pm[(nt << 3) + (lj << 1) + 1];
            float p0 = ex2f(st[nt][0] + pm0);
            float p1 = ex2f(st[nt][1] + pm1);
            float p2 = ex2f(st[nt][2] + pm0);
            float p3 = ex2f(st[nt][3] + pm1);
            if (needmask) {
                if (key0 > qA)     p0 = 0.f;
                if (key0 + 1 > qA) p1 = 0.f;
                if (key0 > qB)     p2 = 0.f;
                if (key0 + 1 > qB) p3 = 0.f;
            }
            __half2 h01 = __floats2half2_rn(p0, p1);
            __half2 h23 = __floats2half2_rn(p2, p3);
            float2 f01 = __half22float2(h01);
            float2 f23 = __half22float2(h23);
            lacc0 += f01.x + f01.y;
            lacc1 += f23.x + f23.y;
            const int ktp = nt >> 1;
            if ((nt & 1) == 0) {
                pa[ktp][0] = *(uint32_t*)&h01;
                pa[ktp][1] = *(uint32_t*)&h23;
            } else {
                pa[ktp][2] = *(uint32_t*)&h01;
                pa[ktp][3] = *(uint32_t*)&h23;
            }
        }

        // ---- O += P[16q x 64k] x V[64k x 64h] ----
        #pragma unroll
        for (int ktp = 0; ktp < 4; ++ktp) {
            const int d0 = (ktp << 4) + (lj << 1);
            #pragma unroll
            for (int nt = 0; nt < 8; ++nt) {
                const int hrow = (nt << 3) + kq;
                uint32_t bb[2];
                bb[0] = *(const uint32_t*)(V + hrow * 72 + d0);
                bb[1] = *(const uint32_t*)(V + hrow * 72 + d0 + 8);
                mma16(o[nt], pa[ktp], bb);
            }
        }
    }

    // ---- partial l: reduce within 4-lane groups, plain store ----
    lacc0 += __shfl_xor_sync(0xFFFFFFFFu, lacc0, 1);
    lacc0 += __shfl_xor_sync(0xFFFFFFFFu, lacc0, 2);
    lacc1 += __shfl_xor_sync(0xFFFFFFFFu, lacc1, 1);
    lacc1 += __shfl_xor_sync(0xFFFFFFFFu, lacc1, 2);
    if (lj == 0) {
        g_pl[seg * B_ * T_ + (size_t)b * T_ + qA] = lacc0;
        g_pl[seg * B_ * T_ + (size_t)b * T_ + qB] = lacc1;
    }

    // ---- partial O: plain stores to slot buffer ----
    {
        float* oA = g_pO + (size_t)seg * B_ * T_ * H_ + ((size_t)b * T_ + qA) * 64;
        float* oB = g_pO + (size_t)seg * B_ * T_ * H_ + ((size_t)b * T_ + qB) * 64;
        #pragma unroll
        for (int nt = 0; nt < 8; ++nt) {
            const int h = (nt << 3) + (lj << 1);
            *(float2*)(oA + h) = make_float2(o[nt][0], o[nt][1]);
            *(float2*)(oB + h) = make_float2(o[nt][2], o[nt][3]);
        }
    }
}

// ---------------- finalize: out = (sum slots O) / (sum slots l) ----------------
__global__ __launch_bounds__(256) void fin_kernel(float* __restrict__ out)
{
    const int idx = blockIdx.x * 256 + threadIdx.x;   // 262144
    const int bt = idx >> 4, h4 = (idx & 15) << 2;
    const int qt = (bt & (T_ - 1)) >> 7;
    const int nseg = (qt >> 3) + 1;

    float l = g_pl[bt];
    float4 v = *(const float4*)(g_pO + (size_t)bt * 64 + h4);
    for (int s = 1; s < nseg; ++s) {
        l += g_pl[s * B_ * T_ + bt];
        const float4 u = *(const float4*)(g_pO + (size_t)s * B_ * T_ * H_ + (size_t)bt * 64 + h4);
        v.x += u.x; v.y += u.y; v.z += u.z; v.w += u.w;
    }
    const float inv = 1.f / l;
    v.x *= inv; v.y *= inv; v.z *= inv; v.w *= inv;
    *(float4*)(out + (size_t)bt * 64 + h4) = v;
}

// ---------------------------------------------------------------------------
extern "C" void kernel_launch(void* const* d_in, const int* in_sizes, int n_in,
                              void* d_out, int out_size)
{
    const float*         x  = (const float*)d_in[0];
    const unsigned char* pm = (const unsigned char*)d_in[1];
    const float*         Wq = (const float*)d_in[2];
    const float*         bq = (const float*)d_in[3];
    const float*         Wk = (const float*)d_in[4];
    const float*         bk = (const float*)d_in[5];
    const float*         Wv = (const float*)d_in[6];
    const float*         bv = (const float*)d_in[7];
    float* out = (float*)d_out;

    prep_kernel<<<384, 256>>>(Wq, Wk, Wv);

    const int qkv_smem = 46080 * 2;    // 92160 B
    cudaFuncSetAttribute(qkv_kernel,
                         cudaFuncAttributeMaxDynamicSharedMemorySize, qkv_smem);
    qkv_kernel<<<(B_ * T_) / 128, 256, qkv_smem>>>(x, bq, bk, bv);

    const int attn_smem = 18432 * 2 + 512;   // 37376 B
    cudaFuncSetAttribute(attn_kernel,
                         cudaFuncAttributeMaxDynamicSharedMemorySize, attn_smem);
    attn_kernel<<<320, 256, attn_smem>>>(pm);

    fin_kernel<<<1024, 256>>>(out);
}

// round 14
// speedup vs baseline: 1.2168x; 1.0276x over previous
#include <cuda_runtime.h>
#include <cuda_fp16.h>
#include <cstdint>
#include <cstddef>

#define B_ 4
#define T_ 4096
#define C_ 512
#define H_ 64
#define NEGB (-1e30f)

__device__ __half g_q[B_*T_*H_];
__device__ __half g_k[B_*T_*H_];
__device__ __half g_v[B_*T_*H_];
__device__ __half g_wh[192 * C_];          // W^T hi, [n 0..191][k 0..511]
__device__ __half g_wl[192 * C_];          // W^T lo
__device__ float  g_pO[4ull * B_*T_*H_];   // per-segment partial O
__device__ float  g_pl[4 * B_*T_];         // per-segment partial l

// ---------------- helpers ----------------
__device__ __forceinline__ float ex2f(float x) {
    float y; asm("ex2.approx.ftz.f32 %0, %1;" : "=f"(y) : "f"(x)); return y;
}
__device__ __forceinline__ void mma16(float* d, const uint32_t* a, const uint32_t* b) {
    asm("mma.sync.aligned.m16n8k16.row.col.f32.f16.f16.f32 "
        "{%0,%1,%2,%3}, {%4,%5,%6,%7}, {%8,%9}, {%0,%1,%2,%3};"
        : "+f"(d[0]), "+f"(d[1]), "+f"(d[2]), "+f"(d[3])
        : "r"(a[0]), "r"(a[1]), "r"(a[2]), "r"(a[3]), "r"(b[0]), "r"(b[1]));
}

// ---------------- prep: split W into hi/lo fp16, transposed [n][k] ----------------
__global__ __launch_bounds__(256) void prep_kernel(
    const float* __restrict__ Wq, const float* __restrict__ Wk, const float* __restrict__ Wv)
{
    const int idx = blockIdx.x * 256 + threadIdx.x;   // 98304 = 192 * 512
    const int n = idx >> 9, k = idx & 511;
    const int m = n >> 6, col = n & 63;
    const float* W = (m == 0) ? Wq : (m == 1) ? Wk : Wv;
    const float v = W[(size_t)k * H_ + col];
    const __half h = __float2half_rn(v);
    g_wh[idx] = h;
    g_wl[idx] = __float2half_rn(v - __half2float(h));
}

// ---------------- QKV projection: 2-term FP16 split (x hi-only) ----------------
// 128 CTAs x 128 rows, 256 threads = 8 warps.
// Warp = (rowgrp = w>>2) 64 rows x (colgrp = w&3) 48 cols: 4 m-tiles x 6 n-tiles.
// acc = xh*wh + xh*wl  (x fp16-rounded; W split hi/lo -> W effectively fp32-exact).
__global__ __launch_bounds__(256) void qkv_kernel(
    const float* __restrict__ x,
    const float* __restrict__ bq, const float* __restrict__ bk, const float* __restrict__ bv)
{
    extern __shared__ __half qsm[];
    __half* xh  = qsm;                 // [128][72]
    __half* wTh = qsm + 9216;          // [192 n][72 k]
    __half* wTl = qsm + 23040;         // [192 n][72 k]   total 36864 halves = 73728 B

    const int t = threadIdx.x, w = t >> 5, lane = t & 31;
    const int kq = lane >> 2, lj = lane & 3;
    const int rowgrp = w >> 2, colgrp = w & 3;
    const int row0 = blockIdx.x << 7;

    float o[24][4];   // [mt*6+nt][4]
    #pragma unroll
    for (int i = 0; i < 24; ++i)
        #pragma unroll
        for (int u = 0; u < 4; ++u) o[i][u] = 0.f;

    for (int kb = 0; kb < 8; ++kb) {
        __syncthreads();
        // ---- stage x slab [128 x 64], fp16 hi only ----
        #pragma unroll
        for (int e = t; e < 2048; e += 256) {
            int row = e >> 4, c4 = (e & 15) << 2;
            float4 v = *(const float4*)(x + (size_t)(row0 + row) * C_ + (kb << 6) + c4);
            *(__half2*)(xh + row * 72 + c4)     = __floats2half2_rn(v.x, v.y);
            *(__half2*)(xh + row * 72 + c4 + 2) = __floats2half2_rn(v.z, v.w);
        }
        // ---- stage W^T slab [192 n x 64 k]: pure uint4 copies from pre-split ----
        #pragma unroll
        for (int e = t; e < 1536; e += 256) {
            int n = e >> 3, u8 = (e & 7) << 3;
            *(uint4*)(wTh + n * 72 + u8) = *(const uint4*)(g_wh + n * C_ + (kb << 6) + u8);
            *(uint4*)(wTl + n * 72 + u8) = *(const uint4*)(g_wl + n * C_ + (kb << 6) + u8);
        }
        __syncthreads();

        // ---- compute: 4 k-steps of 16 ----
        #pragma unroll
        for (int kt = 0; kt < 4; ++kt) {
            const int d0 = (kt << 4) + (lj << 1);
            uint32_t ah[4][4];
            #pragma unroll
            for (int mt = 0; mt < 4; ++mt) {
                const int r0 = (rowgrp << 6) + (mt << 4) + kq;
                ah[mt][0] = *(const uint32_t*)(xh + r0 * 72 + d0);
                ah[mt][1] = *(const uint32_t*)(xh + (r0 + 8) * 72 + d0);
                ah[mt][2] = *(const uint32_t*)(xh + r0 * 72 + d0 + 8);
                ah[mt][3] = *(const uint32_t*)(xh + (r0 + 8) * 72 + d0 + 8);
            }
            #pragma unroll
            for (int nt = 0; nt < 6; ++nt) {
                const int n = colgrp * 48 + (nt << 3) + kq;
                uint32_t bh[2], bl[2];
                bh[0] = *(const uint32_t*)(wTh + n * 72 + d0);
                bh[1] = *(const uint32_t*)(wTh + n * 72 + d0 + 8);
                bl[0] = *(const uint32_t*)(wTl + n * 72 + d0);
                bl[1] = *(const uint32_t*)(wTl + n * 72 + d0 + 8);
                #pragma unroll
                for (int mt = 0; mt < 4; ++mt) {
                    mma16(o[mt * 6 + nt], ah[mt], bh);
                    mma16(o[mt * 6 + nt], ah[mt], bl);
                }
            }
        }
    }

    // ---- epilogue: bias, scale, fp16 store ----
    const float QS = 0.125f * 1.4426950408889634f;  // (1/sqrt(64)) * log2(e)
    #pragma unroll
    for (int mt = 0; mt < 4; ++mt) {
        const int rA = row0 + (rowgrp << 6) + (mt << 4) + kq;
        const int rB = rA + 8;
        #pragma unroll
        for (int nt = 0; nt < 6; ++nt) {
            const int cb = colgrp * 48 + (nt << 3);
            const int m = cb >> 6;
            const int cc = (cb & 63) + (lj << 1);
            const float* bias = (m == 0) ? bq : (m == 1) ? bk : bv;
            __half* dst = (m == 0) ? g_q : (m == 1) ? g_k : g_v;
            const float b0 = bias[cc], b1 = bias[cc + 1];
            float v0 = o[mt * 6 + nt][0] + b0, v1 = o[mt * 6 + nt][1] + b1;
            float v2 = o[mt * 6 + nt][2] + b0, v3 = o[mt * 6 + nt][3] + b1;
            if (m == 0) { v0 *= QS; v1 *= QS; v2 *= QS; v3 *= QS; }
            *(__half2*)(dst + (size_t)rA * H_ + cc) = __floats2half2_rn(v0, v1);
            *(__half2*)(dst + (size_t)rB * H_ + cc) = __floats2half2_rn(v2, v3);
        }
    }
}

// ---------------- schedule: 80 (qtile, seg) units, heaviest first ----------------
__constant__ unsigned char c_sched[80] = {
    28, 60, 61, 88, 92, 93, 94, 120, 121, 124, 125, 126, 127,
    56, 57, 84, 85, 89, 90, 112, 113, 116, 117, 118, 119, 122, 123,
    24, 52, 53, 76, 80, 81, 82, 86, 104, 105, 108, 109, 110, 111, 114, 115,
    48, 49, 72, 73, 77, 78, 96, 97, 100, 101, 102, 103, 106, 107,
    20, 44, 45, 64, 68, 69, 70, 74, 98, 99,
    40, 41, 65, 66,
    16, 36, 37,
    32, 33,
    12, 8, 4, 0
};

// K rows copied fp16 [64 key][72 d]; V transposed fp16 [64 h][72 key] (key-pairs).
__device__ __forceinline__ void load_kv_h(
    __half* Kb, __half* Vb, const __half* kc, const __half* vc, int t)
{
    #pragma unroll
    for (int e = t; e < 512; e += 256) {
        int row = e >> 3, c8 = (e & 7) << 3;
        *(uint4*)(Kb + row * 72 + c8) = *(const uint4*)(kc + row * 64 + c8);
    }
    #pragma unroll
    for (int e = t; e < 512; e += 256) {
        int k2 = e & 31, h4 = (e >> 5) << 2;
        uint2 a0 = *(const uint2*)(vc + (size_t)(2 * k2) * 64 + h4);
        uint2 a1 = *(const uint2*)(vc + (size_t)(2 * k2 + 1) * 64 + h4);
        uint32_t o0 = (a0.x & 0xFFFFu) | (a1.x << 16);
        uint32_t o1 = (a0.x >> 16)     | (a1.x & 0xFFFF0000u);
        uint32_t o2 = (a0.y & 0xFFFFu) | (a1.y << 16);
        uint32_t o3 = (a0.y >> 16)     | (a1.y & 0xFFFF0000u);
        *(uint32_t*)(Vb + (h4 + 0) * 72 + 2 * k2) = o0;
        *(uint32_t*)(Vb + (h4 + 1) * 72 + 2 * k2) = o1;
        *(uint32_t*)(Vb + (h4 + 2) * 72 + 2 * k2) = o2;
        *(uint32_t*)(Vb + (h4 + 3) * 72 + 2 * k2) = o3;
    }
}

// ---------------- fp16 flash attention, partials to slot buffers ----------------
__global__ __launch_bounds__(256, 2) void attn_kernel(const unsigned char* __restrict__ pmask)
{
    extern __shared__ __half smh[];
    __half* Ks = smh;                    // 2 x [64][72]
    __half* Vt = smh + 9216;             // 2 x [64][72]
    float* pmfs = (float*)(smh + 18432); // 2 x [64]

    const int t = threadIdx.x, w = t >> 5, lane = t & 31;
    const int kq = lane >> 2, lj = lane & 3;

    const int bid = blockIdx.x;
    const int e = c_sched[bid >> 2];
    const int qt = e >> 2, seg = e & 3;
    const int b = bid & 3;
    const int nseg = (qt >> 3) + 1;
    const int n = 2 * (qt + 1);
    const int base = n / nseg, rem = n - base * nseg;
    const int cnt = base + (seg < rem ? 1 : 0);
    const int c0 = seg * base + (seg < rem ? seg : rem);

    const int q0 = qt << 7;
    const int qbase = w << 4;
    const int qA = q0 + qbase + kq;
    const int qB = qA + 8;

    const __half* kg = g_k + (size_t)b * T_ * H_;
    const __half* vg = g_v + (size_t)b * T_ * H_;

    // ---- Q A-fragments straight from gmem (constant across chunks) ----
    uint32_t qa[4][4];
    {
        const __half* qra = g_q + ((size_t)b * T_ + qA) * H_;
        const __half* qrb = g_q + ((size_t)b * T_ + qB) * H_;
        #pragma unroll
        for (int kt = 0; kt < 4; ++kt) {
            const int d0 = (kt << 4) + (lj << 1);
            qa[kt][0] = *(const uint32_t*)(qra + d0);
            qa[kt][1] = *(const uint32_t*)(qrb + d0);
            qa[kt][2] = *(const uint32_t*)(qra + d0 + 8);
            qa[kt][3] = *(const uint32_t*)(qrb + d0 + 8);
        }
    }

    load_kv_h(Ks, Vt, kg + (size_t)(c0 << 6) * 64, vg + (size_t)(c0 << 6) * 64, t);
    if (t < 64) pmfs[t] = pmask[(size_t)b * T_ + (c0 << 6) + t] ? NEGB : 0.f;
    __syncthreads();

    float o[8][4];
    #pragma unroll
    for (int nt = 0; nt < 8; ++nt)
        #pragma unroll
        for (int u = 0; u < 4; ++u) o[nt][u] = 0.f;
    float lacc0 = 0.f, lacc1 = 0.f;

    for (int i = 0; i < cnt; ++i) {
        const int buf = i & 1, nbuf = buf ^ 1;
        const int k0 = (c0 + i) << 6;
        if (i) __syncthreads();

        if (i + 1 < cnt) {
            const int k1 = k0 + 64;
            load_kv_h(Ks + nbuf * 4608, Vt + nbuf * 4608,
                      kg + (size_t)k1 * 64, vg + (size_t)k1 * 64, t);
            if (t < 64) pmfs[nbuf * 64 + t] = pmask[(size_t)b * T_ + k1 + t] ? NEGB : 0.f;
        }

        const __half* K = Ks + buf * 4608;
        const __half* V = Vt + buf * 4608;
        const float* pm = pmfs + buf * 64;

        // ---- S[16q x 64key] ----
        float st[8][4];
        #pragma unroll
        for (int nt = 0; nt < 8; ++nt)
            #pragma unroll
            for (int u = 0; u < 4; ++u) st[nt][u] = 0.f;
        #pragma unroll
        for (int kt = 0; kt < 4; ++kt) {
            const int d0 = (kt << 4) + (lj << 1);
            #pragma unroll
            for (int nt = 0; nt < 8; ++nt) {
                const int krow = (nt << 3) + kq;
                uint32_t bb[2];
                bb[0] = *(const uint32_t*)(K + krow * 72 + d0);
                bb[1] = *(const uint32_t*)(K + krow * 72 + d0 + 8);
                mma16(st[nt], qa[kt], bb);
            }
        }

        // ---- softmax (no max) + pack P a-frags in registers ----
        const bool needmask = (k0 + 63) > (q0 + qbase);
        uint32_t pa[4][4];
        #pragma unroll
        for (int nt = 0; nt < 8; ++nt) {
            const int key0 = k0 + (nt << 3) + (lj << 1);
            const float pm0 = pm[(nt << 3) + (lj << 1)];
            const float pm1 = pm[(nt << 3) + (lj << 1) + 1];
            float p0 = ex2f(st[nt][0] + pm0);
            float p1 = ex2f(st[nt][1] + pm1);
            float p2 = ex2f(st[nt][2] + pm0);
            float p3 = ex2f(st[nt][3] + pm1);
            if (needmask) {
                if (key0 > qA)     p0 = 0.f;
                if (key0 + 1 > qA) p1 = 0.f;
                if (key0 > qB)     p2 = 0.f;
                if (key0 + 1 > qB) p3 = 0.f;
            }
            __half2 h01 = __floats2half2_rn(p0, p1);
            __half2 h23 = __floats2half2_rn(p2, p3);
            float2 f01 = __half22float2(h01);
            float2 f23 = __half22float2(h23);
            lacc0 += f01.x + f01.y;
            lacc1 += f23.x + f23.y;
            const int ktp = nt >> 1;
            if ((nt & 1) == 0) {
                pa[ktp][0] = *(uint32_t*)&h01;
                pa[ktp][1] = *(uint32_t*)&h23;
            } else {
                pa[ktp][2] = *(uint32_t*)&h01;
                pa[ktp][3] = *(uint32_t*)&h23;
            }
        }

        // ---- O += P[16q x 64k] x V[64k x 64h] ----
        #pragma unroll
        for (int ktp = 0; ktp < 4; ++ktp) {
            const int d0 = (ktp << 4) + (lj << 1);
            #pragma unroll
            for (int nt = 0; nt < 8; ++nt) {
                const int hrow = (nt << 3) + kq;
                uint32_t bb[2];
                bb[0] = *(const uint32_t*)(V + hrow * 72 + d0);
                bb[1] = *(const uint32_t*)(V + hrow * 72 + d0 + 8);
                mma16(o[nt], pa[ktp], bb);
            }
        }
    }

    // ---- partial l: reduce within 4-lane groups, plain store ----
    lacc0 += __shfl_xor_sync(0xFFFFFFFFu, lacc0, 1);
    lacc0 += __shfl_xor_sync(0xFFFFFFFFu, lacc0, 2);
    lacc1 += __shfl_xor_sync(0xFFFFFFFFu, lacc1, 1);
    lacc1 += __shfl_xor_sync(0xFFFFFFFFu, lacc1, 2);
    if (lj == 0) {
        g_pl[seg * B_ * T_ + (size_t)b * T_ + qA] = lacc0;
        g_pl[seg * B_ * T_ + (size_t)b * T_ + qB] = lacc1;
    }

    // ---- partial O: plain stores to slot buffer ----
    {
        float* oA = g_pO + (size_t)seg * B_ * T_ * H_ + ((size_t)b * T_ + qA) * 64;
        float* oB = g_pO + (size_t)seg * B_ * T_ * H_ + ((size_t)b * T_ + qB) * 64;
        #pragma unroll
        for (int nt = 0; nt < 8; ++nt) {
            const int h = (nt << 3) + (lj << 1);
            *(float2*)(oA + h) = make_float2(o[nt][0], o[nt][1]);
            *(float2*)(oB + h) = make_float2(o[nt][2], o[nt][3]);
        }
    }
}

// ---------------- finalize: out = (sum slots O) / (sum slots l) ----------------
__global__ __launch_bounds__(256) void fin_kernel(float* __restrict__ out)
{
    const int idx = blockIdx.x * 256 + threadIdx.x;   // 262144
    const int bt = idx >> 4, h4 = (idx & 15) << 2;
    const int qt = (bt & (T_ - 1)) >> 7;
    const int nseg = (qt >> 3) + 1;

    float l = g_pl[bt];
    float4 v = *(const float4*)(g_pO + (size_t)bt * 64 + h4);
    for (int s = 1; s < nseg; ++s) {
        l += g_pl[s * B_ * T_ + bt];
        const float4 u = *(const float4*)(g_pO + (size_t)s * B_ * T_ * H_ + (size_t)bt * 64 + h4);
        v.x += u.x; v.y += u.y; v.z += u.z; v.w += u.w;
    }
    const float inv = 1.f / l;
    v.x *= inv; v.y *= inv; v.z *= inv; v.w *= inv;
    *(float4*)(out + (size_t)bt * 64 + h4) = v;
}

// ---------------------------------------------------------------------------
extern "C" void kernel_launch(void* const* d_in, const int* in_sizes, int n_in,
                              void* d_out, int out_size)
{
    const float*         x  = (const float*)d_in[0];
    const unsigned char* pm = (const unsigned char*)d_in[1];
    const float*         Wq = (const float*)d_in[2];
    const float*         bq = (const float*)d_in[3];
    const float*         Wk = (const float*)d_in[4];
    const float*         bk = (const float*)d_in[5];
    const float*         Wv = (const float*)d_in[6];
    const float*         bv = (const float*)d_in[7];
    float* out = (float*)d_out;

    prep_kernel<<<384, 256>>>(Wq, Wk, Wv);

    const int qkv_smem = 36864 * 2;    // 73728 B
    cudaFuncSetAttribute(qkv_kernel,
                         cudaFuncAttributeMaxDynamicSharedMemorySize, qkv_smem);
    qkv_kernel<<<(B_ * T_) / 128, 256, qkv_smem>>>(x, bq, bk, bv);

    const int attn_smem = 18432 * 2 + 512;   // 37376 B
    cudaFuncSetAttribute(attn_kernel,
                         cudaFuncAttributeMaxDynamicSharedMemorySize, attn_smem);
    attn_kernel<<<320, 256, attn_smem>>>(pm);

    fin_kernel<<<1024, 256>>>(out);
}